// round 2
// baseline (speedup 1.0000x reference)
#include <cuda_runtime.h>
#include <cstdint>
#include <cstddef>

// ---------------- problem constants ----------------
#define HEADS   32
#define HDIM    64      // P
#define NSTATE  32
#define KCONV   4
#define DMODEL  2048
#define CONVDIM 2112
#define PROJW   4192
#define BATCH   4
#define LSEQ    2048
#define BL      (BATCH * LSEQ)   // 8192

// ---------------- scratch (device globals; no runtime alloc) ----------------
__device__ float g_proj[(size_t)BL * PROJW];     // 137 MB
__device__ float g_conv[(size_t)BL * CONVDIM];   // 69 MB
__device__ float g_dt  [(size_t)BATCH * HEADS * LSEQ];
__device__ float g_dA  [(size_t)BATCH * HEADS * LSEQ];
__device__ float g_y   [(size_t)BL * DMODEL];    // 67 MB

// ---------------- packed fp32x2 helpers (Blackwell FFMA2) ----------------
__device__ __forceinline__ unsigned long long pack2(float lo, float hi) {
    unsigned long long r;
    asm("mov.b64 %0, {%1, %2};" : "=l"(r) : "f"(lo), "f"(hi));
    return r;
}
__device__ __forceinline__ void fma2(unsigned long long& acc,
                                     unsigned long long a, unsigned long long b) {
    asm("fma.rn.f32x2 %0, %1, %2, %0;" : "+l"(acc) : "l"(a), "l"(b));
}
__device__ __forceinline__ float lo32(unsigned long long v) {
    return __uint_as_float((unsigned)(v & 0xffffffffull));
}
__device__ __forceinline__ float hi32(unsigned long long v) {
    return __uint_as_float((unsigned)(v >> 32));
}

// ---------------- SGEMM: C(M,N) = A(M,K) @ B(K,N) [+ bias] ----------------
// BM=BN=128, BK=8, 256 threads, 8x8 per thread, FFMA2 inner product.
// M % 128 == 0 and K % 8 == 0 assumed (true here). N handled with guards (N%4==0).
__global__ __launch_bounds__(256, 2)
void sgemm128(const float* __restrict__ A, const float* __restrict__ Bm,
              const float* __restrict__ bias, float* __restrict__ C,
              int M, int N, int K)
{
    __shared__ float As[8][128];
    __shared__ float Bs[8][128];

    const int tid  = threadIdx.x;
    const int cRow = blockIdx.y;
    const int cCol = blockIdx.x;

    const int aRow = tid >> 1;            // 0..127
    const int aCol = (tid & 1) << 2;      // 0 or 4
    const int bRow = tid >> 5;            // 0..7
    const int bCol = (tid & 31) << 2;     // 0..124

    const float* Ap = A + (size_t)(cRow * 128 + aRow) * K + aCol;
    const float* Bp = Bm + (size_t)bRow * N + (size_t)cCol * 128 + bCol;
    const bool bOk  = (cCol * 128 + bCol) < N;   // float4 fully in/out (N%4==0)

    const int thR = (tid >> 4) << 3;      // 0..120
    const int thC = (tid & 15) << 3;      // 0..120

    unsigned long long acc[8][4];
    #pragma unroll
    for (int i = 0; i < 8; i++)
        #pragma unroll
        for (int j = 0; j < 4; j++) acc[i][j] = 0ull;

    for (int kt = 0; kt < K; kt += 8) {
        float4 av = *(const float4*)Ap;
        As[aCol + 0][aRow] = av.x;
        As[aCol + 1][aRow] = av.y;
        As[aCol + 2][aRow] = av.z;
        As[aCol + 3][aRow] = av.w;
        float4 bv = bOk ? *(const float4*)Bp : make_float4(0.f, 0.f, 0.f, 0.f);
        *(float4*)&Bs[bRow][bCol] = bv;
        __syncthreads();

        #pragma unroll
        for (int k = 0; k < 8; k++) {
            float4 a0 = *(const float4*)&As[k][thR];
            float4 a1 = *(const float4*)&As[k][thR + 4];
            const unsigned long long* bp64 =
                (const unsigned long long*)&Bs[k][thC];
            unsigned long long b2[4];
            #pragma unroll
            for (int j = 0; j < 4; j++) b2[j] = bp64[j];
            float ar[8] = {a0.x, a0.y, a0.z, a0.w, a1.x, a1.y, a1.z, a1.w};
            #pragma unroll
            for (int i = 0; i < 8; i++) {
                unsigned long long a2 = pack2(ar[i], ar[i]);
                #pragma unroll
                for (int j = 0; j < 4; j++) fma2(acc[i][j], a2, b2[j]);
            }
        }
        __syncthreads();
        Ap += 8;
        Bp += (size_t)8 * N;
    }

    #pragma unroll
    for (int i = 0; i < 8; i++) {
        float* crow = C + (size_t)(cRow * 128 + thR + i) * N + (size_t)cCol * 128 + thC;
        #pragma unroll
        for (int jj = 0; jj < 2; jj++) {
            int col = cCol * 128 + thC + jj * 4;
            if (col < N) {
                float4 r;
                r.x = lo32(acc[i][jj * 2 + 0]);
                r.y = hi32(acc[i][jj * 2 + 0]);
                r.z = lo32(acc[i][jj * 2 + 1]);
                r.w = hi32(acc[i][jj * 2 + 1]);
                if (bias) {
                    r.x += bias[col + 0]; r.y += bias[col + 1];
                    r.z += bias[col + 2]; r.w += bias[col + 3];
                }
                *(float4*)(crow + jj * 4) = r;
            }
        }
    }
}

// ---------------- causal depthwise conv1d (K=4) + SiLU ----------------
__global__ void conv_silu_kernel(const float* __restrict__ conv_w,
                                 const float* __restrict__ conv_b)
{
    int idx = blockIdx.x * blockDim.x + threadIdx.x;
    if (idx >= BL * CONVDIM) return;
    int c = idx % CONVDIM;
    int m = idx / CONVDIM;       // b*L + l
    int l = m % LSEQ;

    float acc = conv_b[c];
    #pragma unroll
    for (int k = 0; k < KCONV; k++) {
        int lk = l - (KCONV - 1) + k;
        if (lk >= 0) {
            acc += g_proj[(size_t)(m - (KCONV - 1) + k) * PROJW + DMODEL + c]
                   * conv_w[c * KCONV + k];
        }
    }
    // SiLU
    acc = acc / (1.f + expf(-acc));
    g_conv[(size_t)m * CONVDIM + c] = acc;
}

// ---------------- dt = softplus(dt_raw + bias), dA = exp(dt*A) ----------------
// stored transposed as (B, H, L) for coalesced scan loads
__global__ void dt_kernel(const float* __restrict__ A_log,
                          const float* __restrict__ dt_bias)
{
    int idx = blockIdx.x * blockDim.x + threadIdx.x;
    if (idx >= BL * HEADS) return;
    int h = idx % HEADS;
    int m = idx / HEADS;         // b*L + l
    int b = m / LSEQ;
    int l = m % LSEQ;

    float raw = g_proj[(size_t)m * PROJW + DMODEL + CONVDIM + h] + dt_bias[h];
    float dt  = (raw > 20.f) ? raw : log1pf(expf(raw));
    float dA  = expf(dt * (-expf(A_log[h])));
    size_t o  = ((size_t)(b * HEADS + h)) * LSEQ + l;
    g_dt[o] = dt;
    g_dA[o] = dA;
}

// ---------------- selective scan ----------------
// one block per (b,h); 512 threads; thread owns (p = tid>>3, n in [4*(tid&7), +4))
// per-step tile (x:64 | B:32 | C:32) streamed via depth-8 cp.async ring.
#define SCAN_DEPTH 8

__global__ __launch_bounds__(512, 1)
void scan_kernel(const float* __restrict__ D_param)
{
    const int h   = blockIdx.x;
    const int b   = blockIdx.y;
    const int tid = threadIdx.x;

    __shared__ float s_dt[LSEQ];
    __shared__ float s_dA[LSEQ];
    __shared__ __align__(16) float s_pipe[SCAN_DEPTH][128];

    // preload dt / dA for the whole sequence (coalesced: layout (B,H,L))
    {
        const float* dtp = g_dt + ((size_t)(b * HEADS + h)) * LSEQ;
        const float* dAp = g_dA + ((size_t)(b * HEADS + h)) * LSEQ;
        for (int i = tid; i < LSEQ; i += 512) {
            s_dt[i] = dtp[i];
            s_dA[i] = dAp[i];
        }
    }

    const int p  = tid >> 3;
    const int ng = tid & 7;
    const float Dh = D_param[h];

    float hs0 = 0.f, hs1 = 0.f, hs2 = 0.f, hs3 = 0.f;

    const bool loader = (tid < 32);
    size_t srcoff = 0; int dstoff = 0;
    if (loader) {
        if (tid < 16) { srcoff = (size_t)h * HDIM + tid * 4; dstoff = tid * 4; }
        else          { srcoff = (size_t)DMODEL + (tid - 16) * 4; dstoff = 64 + (tid - 16) * 4; }
    }
    const float* convb = g_conv + (size_t)b * LSEQ * CONVDIM;
    unsigned sbase = (unsigned)__cvta_generic_to_shared(&s_pipe[0][0]);

    // prologue: issue loads for t = 0 .. SCAN_DEPTH-2
    #pragma unroll
    for (int t = 0; t < SCAN_DEPTH - 1; t++) {
        if (loader) {
            const float* src = convb + (size_t)t * CONVDIM + srcoff;
            unsigned dst = sbase + (unsigned)((t & (SCAN_DEPTH - 1)) * 128 + dstoff) * 4u;
            asm volatile("cp.async.ca.shared.global [%0], [%1], 16;\n"
                         :: "r"(dst), "l"(src));
        }
        asm volatile("cp.async.commit_group;\n" ::: "memory");
    }

    for (int t = 0; t < LSEQ; t++) {
        const int nt = t + SCAN_DEPTH - 1;
        if (loader && nt < LSEQ) {
            const float* src = convb + (size_t)nt * CONVDIM + srcoff;
            unsigned dst = sbase + (unsigned)((nt & (SCAN_DEPTH - 1)) * 128 + dstoff) * 4u;
            asm volatile("cp.async.ca.shared.global [%0], [%1], 16;\n"
                         :: "r"(dst), "l"(src));
        }
        asm volatile("cp.async.commit_group;\n" ::: "memory");
        asm volatile("cp.async.wait_group 7;\n" ::: "memory");
        __syncthreads();   // data for t visible; prior compute done

        const float* sl = s_pipe[t & (SCAN_DEPTH - 1)];
        float dtv = s_dt[t];
        float dav = s_dA[t];
        float xv  = sl[p];
        float4 Bv = *(const float4*)&sl[64 + ng * 4];
        float4 Cv = *(const float4*)&sl[96 + ng * 4];

        float coef = dtv * xv;
        hs0 = dav * hs0 + coef * Bv.x;
        hs1 = dav * hs1 + coef * Bv.y;
        hs2 = dav * hs2 + coef * Bv.z;
        hs3 = dav * hs3 + coef * Bv.w;

        float acc = hs0 * Cv.x + hs1 * Cv.y + hs2 * Cv.z + hs3 * Cv.w;
        acc += __shfl_xor_sync(0xffffffffu, acc, 1);
        acc += __shfl_xor_sync(0xffffffffu, acc, 2);
        acc += __shfl_xor_sync(0xffffffffu, acc, 4);
        if (ng == 0) {
            g_y[((size_t)(b * LSEQ + t)) * DMODEL + h * HDIM + p] = acc + Dh * xv;
        }
        __syncthreads();   // slot t%DEPTH free for reuse next iter
    }
}

// ---------------- gated RMSNorm (in place on g_y) ----------------
__global__ __launch_bounds__(256)
void rmsnorm_kernel(const float* __restrict__ norm_w)
{
    const int m   = blockIdx.x;
    const int tid = threadIdx.x;
    float*       yrow = g_y    + (size_t)m * DMODEL;
    const float* grow = g_proj + (size_t)m * PROJW;   // gate = proj[:, 0:2048]

    float v[8];
    float ss = 0.f;
    #pragma unroll
    for (int k = 0; k < 8; k++) {
        int j = tid + k * 256;
        float g   = grow[j];
        float val = yrow[j] * (g / (1.f + expf(-g)));
        v[k] = val;
        ss += val * val;
    }
    #pragma unroll
    for (int o = 16; o > 0; o >>= 1) ss += __shfl_xor_sync(0xffffffffu, ss, o);

    __shared__ float sred[8];
    if ((tid & 31) == 0) sred[tid >> 5] = ss;
    __syncthreads();
    float tot = sred[0] + sred[1] + sred[2] + sred[3]
              + sred[4] + sred[5] + sred[6] + sred[7];
    float scale = rsqrtf(tot * (1.f / DMODEL) + 1e-6f);

    #pragma unroll
    for (int k = 0; k < 8; k++) {
        int j = tid + k * 256;
        yrow[j] = v[k] * scale * norm_w[j];
    }
}

// ---------------- launch ----------------
extern "C" void kernel_launch(void* const* d_in, const int* in_sizes, int n_in,
                              void* d_out, int out_size)
{
    const float* x       = (const float*)d_in[0];
    const float* W_in    = (const float*)d_in[1];
    const float* b_in    = (const float*)d_in[2];
    const float* conv_w  = (const float*)d_in[3];
    const float* conv_b  = (const float*)d_in[4];
    const float* A_log   = (const float*)d_in[5];
    const float* dt_bias = (const float*)d_in[6];
    const float* D_par   = (const float*)d_in[7];
    const float* norm_w  = (const float*)d_in[8];
    const float* W_out   = (const float*)d_in[9];
    float* out = (float*)d_out;

    float *proj, *yb;
    cudaGetSymbolAddress((void**)&proj, g_proj);
    cudaGetSymbolAddress((void**)&yb,   g_y);

    // 1) proj = x @ W_in + b_in        (8192 x 4192, K=2048)
    {
        dim3 grid((PROJW + 127) / 128, BL / 128);
        sgemm128<<<grid, 256>>>(x, W_in, b_in, proj, BL, PROJW, DMODEL);
    }
    // 2) causal depthwise conv + SiLU
    {
        int total = BL * CONVDIM;
        conv_silu_kernel<<<(total + 255) / 256, 256>>>(conv_w, conv_b);
    }
    // 3) dt / dA
    {
        int total = BL * HEADS;
        dt_kernel<<<(total + 255) / 256, 256>>>(A_log, dt_bias);
    }
    // 4) selective scan (+ D skip)
    scan_kernel<<<dim3(HEADS, BATCH), 512>>>(D_par);
    // 5) gated RMSNorm
    rmsnorm_kernel<<<BL, 256>>>(norm_w);
    // 6) out = y @ W_out               (8192 x 2048, K=2048)
    {
        dim3 grid(DMODEL / 128, BL / 128);
        sgemm128<<<grid, 256>>>(yb, W_out, nullptr, out, BL, DMODEL, DMODEL);
    }
}

// round 3
// speedup vs baseline: 4.8047x; 4.8047x over previous
#include <cuda_runtime.h>
#include <cstdint>
#include <cstddef>

// ---------------- problem constants ----------------
#define HEADS   32
#define HDIM    64      // P
#define NSTATE  32
#define KCONV   4
#define DMODEL  2048
#define CONVDIM 2112
#define PROJW   4192
#define BATCH   4
#define LSEQ    2048
#define BL      (BATCH * LSEQ)   // 8192

// ---------------- scratch (device globals; no runtime alloc) ----------------
__device__ float g_proj[(size_t)BL * PROJW];     // 137 MB
__device__ float g_conv[(size_t)BL * CONVDIM];   // 69 MB
__device__ float g_dt  [(size_t)BATCH * HEADS * LSEQ];
__device__ float g_dA  [(size_t)BATCH * HEADS * LSEQ];
__device__ float g_y   [(size_t)BL * DMODEL];    // 67 MB (tf32-rounded by rmsnorm)
__device__ float g_xa  [(size_t)BL * DMODEL];    // 67 MB (tf32-rounded x)
__device__ float g_wa  [(size_t)DMODEL * PROJW]; // 34 MB (tf32-rounded W_in)
__device__ float g_wb  [(size_t)DMODEL * DMODEL];// 17 MB (tf32-rounded W_out)

// ---------------- packed fp32x2 helpers ----------------
__device__ __forceinline__ unsigned long long pack2(float lo, float hi) {
    unsigned long long r;
    asm("mov.b64 %0, {%1, %2};" : "=l"(r) : "f"(lo), "f"(hi));
    return r;
}
__device__ __forceinline__ unsigned long long mul2(unsigned long long a, unsigned long long b) {
    unsigned long long r;
    asm("mul.rn.f32x2 %0, %1, %2;" : "=l"(r) : "l"(a), "l"(b));
    return r;
}
__device__ __forceinline__ unsigned long long fma2v(unsigned long long a, unsigned long long b,
                                                    unsigned long long c) {
    unsigned long long r;
    asm("fma.rn.f32x2 %0, %1, %2, %3;" : "=l"(r) : "l"(a), "l"(b), "l"(c));
    return r;
}
__device__ __forceinline__ unsigned long long add2(unsigned long long a, unsigned long long b) {
    unsigned long long r;
    asm("add.rn.f32x2 %0, %1, %2;" : "=l"(r) : "l"(a), "l"(b));
    return r;
}
__device__ __forceinline__ float lo32(unsigned long long v) {
    return __uint_as_float((unsigned)(v & 0xffffffffull));
}
__device__ __forceinline__ float hi32(unsigned long long v) {
    return __uint_as_float((unsigned)(v >> 32));
}
__device__ __forceinline__ float tf32r(float x) {
    unsigned r;
    asm("cvt.rna.tf32.f32 %0, %1;" : "=r"(r) : "f"(x));
    return __uint_as_float(r);
}

// ---------------- tf32 rounding pass ----------------
__global__ void round_tf32_kernel(const float* __restrict__ in, float* __restrict__ out, int n4)
{
    int i = blockIdx.x * blockDim.x + threadIdx.x;
    if (i >= n4) return;
    float4 v = ((const float4*)in)[i];
    v.x = tf32r(v.x); v.y = tf32r(v.y); v.z = tf32r(v.z); v.w = tf32r(v.w);
    ((float4*)out)[i] = v;
}

// ---------------- TF32 tensor-core GEMM ----------------
// C(M,N) = A(M,K) @ B(K,N) [+bias], A/B pre-rounded to tf32, fp32 accum.
// 128x128x16 block tile, 8 warps (warp tile 64x32), mma.m16n8k8, double-buffered cp.async.
#define CP16(dst, src, bytes) \
    asm volatile("cp.async.cg.shared.global [%0], [%1], 16, %2;\n" \
                 :: "r"(dst), "l"(src), "r"(bytes))

__global__ void __launch_bounds__(256)
mma_gemm(const float* __restrict__ A, const float* __restrict__ B,
         const float* __restrict__ bias, float* __restrict__ C,
         int M, int N, int K)
{
    __shared__ __align__(16) float As[2][128][20];   // [buf][m][k], pad->conflict-free frags
    __shared__ __align__(16) float Bs[2][16][136];   // [buf][k][n], pad 8

    const int tid  = threadIdx.x;
    const int bx   = blockIdx.x;   // N tile
    const int by   = blockIdx.y;   // M tile
    const int warp = tid >> 5;
    const int lane = tid & 31;
    const int g    = lane >> 2;    // groupID
    const int t    = lane & 3;     // threadID_in_group
    const int wm   = (warp & 1) * 64;
    const int wn   = (warp >> 1) * 32;

    // loader mapping
    const int arow  = tid >> 2;          // 0..63 (second load: +64)
    const int acseg = tid & 3;
    const int brow  = tid >> 5;          // 0..7  (second load: +8)
    const int bcseg = tid & 31;
    const int bcol  = bx * 128 + bcseg * 4;
    const int bb    = (bcol + 4 <= N) ? 16 : 0;

    const float* Abase = A + (size_t)(by * 128 + arow) * K + acseg * 4;
    const float* Bbase = B + (size_t)brow * N + (bb ? bcol : 0);

    unsigned asB = (unsigned)__cvta_generic_to_shared(&As[0][0][0]);
    unsigned bsB = (unsigned)__cvta_generic_to_shared(&Bs[0][0][0]);
    const unsigned aOff = (unsigned)(arow * 20 + acseg * 4) * 4u;
    const unsigned bOff = (unsigned)(brow * 136 + bcseg * 4) * 4u;

#define ISSUE_TILE(kt, buf) do {                                              \
    const float* asrc = Abase + (size_t)(kt) * 16;                            \
    unsigned ad = asB + (unsigned)(buf) * (128u*20u*4u) + aOff;               \
    CP16(ad, asrc, 16);                                                       \
    CP16(ad + 64u*20u*4u, asrc + (size_t)64 * K, 16);                         \
    const float* bsrc = Bbase + (size_t)(kt) * 16 * N;                        \
    unsigned bd = bsB + (unsigned)(buf) * (16u*136u*4u) + bOff;               \
    CP16(bd, bsrc, bb);                                                       \
    CP16(bd + 8u*136u*4u, bsrc + (size_t)8 * N, bb);                          \
    asm volatile("cp.async.commit_group;\n" ::: "memory");                    \
} while (0)

    float c[16][4];
    #pragma unroll
    for (int i = 0; i < 16; i++)
        #pragma unroll
        for (int j = 0; j < 4; j++) c[i][j] = 0.f;

    const int nt = K >> 4;
    ISSUE_TILE(0, 0);

    for (int kt = 0; kt < nt; kt++) {
        const int buf = kt & 1;
        if (kt + 1 < nt) {
            ISSUE_TILE(kt + 1, buf ^ 1);
            asm volatile("cp.async.wait_group 1;\n" ::: "memory");
        } else {
            asm volatile("cp.async.wait_group 0;\n" ::: "memory");
        }
        __syncthreads();

        #pragma unroll
        for (int ks = 0; ks < 2; ks++) {
            const int k0 = ks * 8;
            unsigned a[4][4], b[4][2];
            #pragma unroll
            for (int i = 0; i < 4; i++) {
                const int r = wm + i * 16 + g;
                a[i][0] = __float_as_uint(As[buf][r    ][k0 + t]);
                a[i][1] = __float_as_uint(As[buf][r + 8][k0 + t]);
                a[i][2] = __float_as_uint(As[buf][r    ][k0 + t + 4]);
                a[i][3] = __float_as_uint(As[buf][r + 8][k0 + t + 4]);
            }
            #pragma unroll
            for (int j = 0; j < 4; j++) {
                const int cn = wn + j * 8 + g;
                b[j][0] = __float_as_uint(Bs[buf][k0 + t    ][cn]);
                b[j][1] = __float_as_uint(Bs[buf][k0 + t + 4][cn]);
            }
            #pragma unroll
            for (int i = 0; i < 4; i++)
                #pragma unroll
                for (int j = 0; j < 4; j++) {
                    asm volatile(
                        "mma.sync.aligned.m16n8k8.row.col.f32.tf32.tf32.f32 "
                        "{%0,%1,%2,%3}, {%4,%5,%6,%7}, {%8,%9}, {%0,%1,%2,%3};\n"
                        : "+f"(c[i*4+j][0]), "+f"(c[i*4+j][1]),
                          "+f"(c[i*4+j][2]), "+f"(c[i*4+j][3])
                        : "r"(a[i][0]), "r"(a[i][1]), "r"(a[i][2]), "r"(a[i][3]),
                          "r"(b[j][0]), "r"(b[j][1]));
                }
        }
        __syncthreads();
    }

    // epilogue
    #pragma unroll
    for (int i = 0; i < 4; i++) {
        #pragma unroll
        for (int j = 0; j < 4; j++) {
            const int row = by * 128 + wm + i * 16 + g;
            const int col = bx * 128 + wn + j * 8 + 2 * t;
            if (col < N) {
                float b0 = 0.f, b1 = 0.f;
                if (bias) { b0 = __ldg(&bias[col]); b1 = __ldg(&bias[col + 1]); }
                float2 v0 = make_float2(c[i*4+j][0] + b0, c[i*4+j][1] + b1);
                float2 v1 = make_float2(c[i*4+j][2] + b0, c[i*4+j][3] + b1);
                *(float2*)&C[(size_t)row * N + col]       = v0;
                *(float2*)&C[(size_t)(row + 8) * N + col] = v1;
            }
        }
    }
#undef ISSUE_TILE
}

// ---------------- causal depthwise conv1d (K=4) + SiLU ----------------
__global__ void conv_silu_kernel(const float* __restrict__ conv_w,
                                 const float* __restrict__ conv_b)
{
    int idx = blockIdx.x * blockDim.x + threadIdx.x;
    if (idx >= BL * CONVDIM) return;
    int c = idx % CONVDIM;
    int m = idx / CONVDIM;       // b*L + l
    int l = m % LSEQ;

    float acc = conv_b[c];
    #pragma unroll
    for (int k = 0; k < KCONV; k++) {
        int lk = l - (KCONV - 1) + k;
        if (lk >= 0) {
            acc += g_proj[(size_t)(m - (KCONV - 1) + k) * PROJW + DMODEL + c]
                   * conv_w[c * KCONV + k];
        }
    }
    acc = acc / (1.f + expf(-acc));
    g_conv[(size_t)m * CONVDIM + c] = acc;
}

// ---------------- dt = softplus(dt_raw + bias), dA = exp(dt*A) ----------------
__global__ void dt_kernel(const float* __restrict__ A_log,
                          const float* __restrict__ dt_bias)
{
    int idx = blockIdx.x * blockDim.x + threadIdx.x;
    if (idx >= BL * HEADS) return;
    int h = idx % HEADS;
    int m = idx / HEADS;
    int b = m / LSEQ;
    int l = m % LSEQ;

    float raw = g_proj[(size_t)m * PROJW + DMODEL + CONVDIM + h] + dt_bias[h];
    float dt  = (raw > 20.f) ? raw : log1pf(expf(raw));
    float dA  = expf(dt * (-expf(A_log[h])));
    size_t o  = ((size_t)(b * HEADS + h)) * LSEQ + l;
    g_dt[o] = dt;
    g_dA[o] = dA;
}

// ---------------- selective scan ----------------
// one block per (b,h); 64 threads; thread owns p=tid and ALL 32 n-states as
// 16 f32x2 register pairs. No shuffles. Operands streamed via depth-8 cp.async.
#define SD 8

__global__ __launch_bounds__(64, 1)
void scan_kernel(const float* __restrict__ D_param)
{
    const int h   = blockIdx.x;
    const int b   = blockIdx.y;
    const int tid = threadIdx.x;

    __shared__ float s_dt[LSEQ];
    __shared__ float s_dA[LSEQ];
    __shared__ __align__(16) float s_pipe[SD][128];

    {
        const float* dtp = g_dt + ((size_t)(b * HEADS + h)) * LSEQ;
        const float* dAp = g_dA + ((size_t)(b * HEADS + h)) * LSEQ;
        for (int i = tid; i < LSEQ; i += 64) {
            s_dt[i] = dtp[i];
            s_dA[i] = dAp[i];
        }
    }

    const float Dh = D_param[h];
    unsigned long long hs[16];
    #pragma unroll
    for (int i = 0; i < 16; i++) hs[i] = 0ull;

    const bool loader = (tid < 32);
    size_t srcoff = 0; int dstoff = 0;
    if (loader) {
        if (tid < 16) { srcoff = (size_t)h * HDIM + tid * 4; dstoff = tid * 4; }
        else          { srcoff = (size_t)DMODEL + (tid - 16) * 4; dstoff = 64 + (tid - 16) * 4; }
    }
    const float* convb = g_conv + (size_t)b * LSEQ * CONVDIM;
    unsigned sbase = (unsigned)__cvta_generic_to_shared(&s_pipe[0][0]);

    #pragma unroll
    for (int tt = 0; tt < SD - 1; tt++) {
        if (loader) {
            const float* src = convb + (size_t)tt * CONVDIM + srcoff;
            unsigned dst = sbase + (unsigned)((tt & (SD - 1)) * 128 + dstoff) * 4u;
            asm volatile("cp.async.ca.shared.global [%0], [%1], 16;\n"
                         :: "r"(dst), "l"(src));
        }
        asm volatile("cp.async.commit_group;\n" ::: "memory");
    }

    float* yout = g_y + (size_t)b * LSEQ * DMODEL + h * HDIM + tid;

    for (int tc = 0; tc < LSEQ; tc++) {
        const int nt = tc + SD - 1;
        if (loader && nt < LSEQ) {
            const float* src = convb + (size_t)nt * CONVDIM + srcoff;
            unsigned dst = sbase + (unsigned)((nt & (SD - 1)) * 128 + dstoff) * 4u;
            asm volatile("cp.async.ca.shared.global [%0], [%1], 16;\n"
                         :: "r"(dst), "l"(src));
        }
        asm volatile("cp.async.commit_group;\n" ::: "memory");
        asm volatile("cp.async.wait_group 7;\n" ::: "memory");
        __syncthreads();

        const float* sl = s_pipe[tc & (SD - 1)];
        float xv  = sl[tid];
        float dtv = s_dt[tc];
        float dav = s_dA[tc];
        float coef = dtv * xv;
        unsigned long long c2 = pack2(coef, coef);
        unsigned long long d2 = pack2(dav, dav);
        const unsigned long long* B2 = (const unsigned long long*)(sl + 64);
        const unsigned long long* C2 = (const unsigned long long*)(sl + 96);

        unsigned long long acc[4] = {0ull, 0ull, 0ull, 0ull};
        #pragma unroll
        for (int i = 0; i < 16; i++) {
            unsigned long long u = mul2(c2, B2[i]);
            hs[i] = fma2v(d2, hs[i], u);
            acc[i & 3] = fma2v(hs[i], C2[i], acc[i & 3]);
        }
        unsigned long long s01 = add2(acc[0], acc[1]);
        unsigned long long s23 = add2(acc[2], acc[3]);
        unsigned long long s   = add2(s01, s23);
        yout[(size_t)tc * DMODEL] = lo32(s) + hi32(s) + Dh * xv;
        __syncthreads();
    }
}

// ---------------- gated RMSNorm (in place; output tf32-rounded for GEMM2) ----------------
__global__ void __launch_bounds__(256)
rmsnorm_kernel(const float* __restrict__ norm_w)
{
    const int m   = blockIdx.x;
    const int tid = threadIdx.x;
    float*       yrow = g_y    + (size_t)m * DMODEL;
    const float* grow = g_proj + (size_t)m * PROJW;   // gate = proj[:, 0:2048]

    float v[8];
    float ss = 0.f;
    #pragma unroll
    for (int k = 0; k < 8; k++) {
        int j = tid + k * 256;
        float gt  = grow[j];
        float val = yrow[j] * (gt / (1.f + expf(-gt)));
        v[k] = val;
        ss += val * val;
    }
    #pragma unroll
    for (int o = 16; o > 0; o >>= 1) ss += __shfl_xor_sync(0xffffffffu, ss, o);

    __shared__ float sred[8];
    if ((tid & 31) == 0) sred[tid >> 5] = ss;
    __syncthreads();
    float tot = sred[0] + sred[1] + sred[2] + sred[3]
              + sred[4] + sred[5] + sred[6] + sred[7];
    float scale = rsqrtf(tot * (1.f / DMODEL) + 1e-6f);

    #pragma unroll
    for (int k = 0; k < 8; k++) {
        int j = tid + k * 256;
        yrow[j] = tf32r(v[k] * scale * norm_w[j]);
    }
}

// ---------------- launch ----------------
extern "C" void kernel_launch(void* const* d_in, const int* in_sizes, int n_in,
                              void* d_out, int out_size)
{
    const float* x       = (const float*)d_in[0];
    const float* W_in    = (const float*)d_in[1];
    const float* b_in    = (const float*)d_in[2];
    const float* conv_w  = (const float*)d_in[3];
    const float* conv_b  = (const float*)d_in[4];
    const float* A_log   = (const float*)d_in[5];
    const float* dt_bias = (const float*)d_in[6];
    const float* D_par   = (const float*)d_in[7];
    const float* norm_w  = (const float*)d_in[8];
    const float* W_out   = (const float*)d_in[9];
    float* out = (float*)d_out;

    float *proj, *yb, *xa, *wa, *wb;
    cudaGetSymbolAddress((void**)&proj, g_proj);
    cudaGetSymbolAddress((void**)&yb,   g_y);
    cudaGetSymbolAddress((void**)&xa,   g_xa);
    cudaGetSymbolAddress((void**)&wa,   g_wa);
    cudaGetSymbolAddress((void**)&wb,   g_wb);

    // 0) tf32-round GEMM operands
    {
        int n4x = (BL * DMODEL) / 4;
        round_tf32_kernel<<<(n4x + 255) / 256, 256>>>(x, xa, n4x);
        int n4a = (DMODEL * PROJW) / 4;
        round_tf32_kernel<<<(n4a + 255) / 256, 256>>>(W_in, wa, n4a);
        int n4b = (DMODEL * DMODEL) / 4;
        round_tf32_kernel<<<(n4b + 255) / 256, 256>>>(W_out, wb, n4b);
    }
    // 1) proj = x @ W_in + b_in        (8192 x 4192, K=2048)
    {
        dim3 grid((PROJW + 127) / 128, BL / 128);
        mma_gemm<<<grid, 256>>>(xa, wa, b_in, proj, BL, PROJW, DMODEL);
    }
    // 2) causal depthwise conv + SiLU
    {
        int total = BL * CONVDIM;
        conv_silu_kernel<<<(total + 255) / 256, 256>>>(conv_w, conv_b);
    }
    // 3) dt / dA
    {
        int total = BL * HEADS;
        dt_kernel<<<(total + 255) / 256, 256>>>(A_log, dt_bias);
    }
    // 4) selective scan (+ D skip)
    scan_kernel<<<dim3(HEADS, BATCH), 64>>>(D_par);
    // 5) gated RMSNorm (tf32-rounds y)
    rmsnorm_kernel<<<BL, 256>>>(norm_w);
    // 6) out = y @ W_out               (8192 x 2048, K=2048)
    {
        dim3 grid(DMODEL / 128, BL / 128);
        mma_gemm<<<grid, 256>>>(yb, wb, nullptr, out, BL, DMODEL, DMODEL);
    }
}

// round 4
// speedup vs baseline: 5.0816x; 1.0576x over previous
#include <cuda_runtime.h>
#include <cstdint>
#include <cstddef>

// ---------------- problem constants ----------------
#define HEADS   32
#define HDIM    64      // P
#define NSTATE  32
#define KCONV   4
#define DMODEL  2048
#define CONVDIM 2112
#define PROJW   4192
#define BATCH   4
#define LSEQ    2048
#define BL      (BATCH * LSEQ)   // 8192

// ---------------- scratch (device globals; no runtime alloc) ----------------
__device__ float g_proj[(size_t)BL * PROJW];     // 137 MB
__device__ float g_conv[(size_t)BL * CONVDIM];   // 69 MB
__device__ float g_dt  [(size_t)BATCH * HEADS * LSEQ];
__device__ float g_dA  [(size_t)BATCH * HEADS * LSEQ];
__device__ float g_y   [(size_t)BL * DMODEL];    // 67 MB (tf32-rounded by rmsnorm)
__device__ float g_xa  [(size_t)BL * DMODEL];    // tf32-rounded x
__device__ float g_wa  [(size_t)DMODEL * PROJW]; // tf32-rounded W_in
__device__ float g_wb  [(size_t)DMODEL * DMODEL];// tf32-rounded W_out

// ---------------- packed fp32x2 helpers ----------------
__device__ __forceinline__ unsigned long long pack2(float lo, float hi) {
    unsigned long long r;
    asm("mov.b64 %0, {%1, %2};" : "=l"(r) : "f"(lo), "f"(hi));
    return r;
}
__device__ __forceinline__ unsigned long long mul2(unsigned long long a, unsigned long long b) {
    unsigned long long r;
    asm("mul.rn.f32x2 %0, %1, %2;" : "=l"(r) : "l"(a), "l"(b));
    return r;
}
__device__ __forceinline__ unsigned long long fma2v(unsigned long long a, unsigned long long b,
                                                    unsigned long long c) {
    unsigned long long r;
    asm("fma.rn.f32x2 %0, %1, %2, %3;" : "=l"(r) : "l"(a), "l"(b), "l"(c));
    return r;
}
__device__ __forceinline__ unsigned long long add2(unsigned long long a, unsigned long long b) {
    unsigned long long r;
    asm("add.rn.f32x2 %0, %1, %2;" : "=l"(r) : "l"(a), "l"(b));
    return r;
}
__device__ __forceinline__ float lo32(unsigned long long v) {
    return __uint_as_float((unsigned)(v & 0xffffffffull));
}
__device__ __forceinline__ float hi32(unsigned long long v) {
    return __uint_as_float((unsigned)(v >> 32));
}
__device__ __forceinline__ float tf32r(float x) {
    unsigned r;
    asm("cvt.rna.tf32.f32 %0, %1;" : "=r"(r) : "f"(x));
    return __uint_as_float(r);
}

// ---------------- tf32 rounding pass ----------------
__global__ void round_tf32_kernel(const float* __restrict__ in, float* __restrict__ out, int n4)
{
    int i = blockIdx.x * blockDim.x + threadIdx.x;
    if (i >= n4) return;
    float4 v = ((const float4*)in)[i];
    v.x = tf32r(v.x); v.y = tf32r(v.y); v.z = tf32r(v.z); v.w = tf32r(v.w);
    ((float4*)out)[i] = v;
}

// ---------------- TF32 tensor-core GEMM ----------------
// C(M,N) = A(M,K) @ B(K,N) [+bias], A/B pre-rounded to tf32, fp32 accum.
// 128x128x16 block tile, 8 warps (warp tile 64x32), mma.m16n8k8.
// 4-stage cp.async ring in DYNAMIC smem, ONE __syncthreads per k-tile.
#define STAGES      4
#define STAGE_FLTS  4736            // 128*20 (A) + 16*136 (B)
#define A_FLTS      2560
#define GEMM_SMEM   (STAGES * STAGE_FLTS * 4)

#define CP16(dst, src, bytes) \
    asm volatile("cp.async.cg.shared.global [%0], [%1], 16, %2;\n" \
                 :: "r"(dst), "l"(src), "r"(bytes))

__global__ void __launch_bounds__(256)
mma_gemm(const float* __restrict__ A, const float* __restrict__ B,
         const float* __restrict__ bias, float* __restrict__ C,
         int M, int N, int K)
{
    extern __shared__ __align__(16) float smem[];

    const int tid  = threadIdx.x;
    const int bx   = blockIdx.x;   // N tile
    const int by   = blockIdx.y;   // M tile
    const int warp = tid >> 5;
    const int lane = tid & 31;
    const int g    = lane >> 2;    // groupID
    const int t    = lane & 3;     // threadID_in_group
    const int wm   = (warp & 1) * 64;
    const int wn   = (warp >> 1) * 32;

    // loader mapping
    const int arow  = tid >> 2;          // 0..63 (second load: +64)
    const int acseg = tid & 3;
    const int brow  = tid >> 5;          // 0..7  (second load: +8)
    const int bcseg = tid & 31;
    const int bcol  = bx * 128 + bcseg * 4;
    const int bb    = (bcol + 4 <= N) ? 16 : 0;

    const float* Abase = A + (size_t)(by * 128 + arow) * K + acseg * 4;
    const float* Bbase = B + (size_t)brow * N + (bb ? bcol : 0);

    unsigned sB = (unsigned)__cvta_generic_to_shared(&smem[0]);
    const unsigned aOff = (unsigned)(arow * 20 + acseg * 4) * 4u;
    const unsigned bOff = (unsigned)(A_FLTS + brow * 136 + bcseg * 4) * 4u;

#define ISSUE_TILE(kt) do {                                                   \
    const unsigned stOff = (unsigned)((kt) & (STAGES - 1)) * (STAGE_FLTS * 4u);\
    const float* asrc = Abase + (size_t)(kt) * 16;                            \
    unsigned ad = sB + stOff + aOff;                                          \
    CP16(ad, asrc, 16);                                                       \
    CP16(ad + 64u*20u*4u, asrc + (size_t)64 * K, 16);                         \
    const float* bsrc = Bbase + (size_t)(kt) * 16 * N;                        \
    unsigned bd = sB + stOff + bOff;                                          \
    CP16(bd, bsrc, bb);                                                       \
    CP16(bd + 8u*136u*4u, bsrc + (size_t)8 * N, bb);                          \
    asm volatile("cp.async.commit_group;\n" ::: "memory");                    \
} while (0)

    float c[16][4];
    #pragma unroll
    for (int i = 0; i < 16; i++)
        #pragma unroll
        for (int j = 0; j < 4; j++) c[i][j] = 0.f;

    const int nt = K >> 4;

    ISSUE_TILE(0);
    ISSUE_TILE(1);
    ISSUE_TILE(2);

    for (int kt = 0; kt < nt; kt++) {
        asm volatile("cp.async.wait_group 2;\n" ::: "memory");   // tile kt ready
        __syncthreads();

        if (kt + 3 < nt) {
            ISSUE_TILE(kt + 3);   // overwrites slot of tile kt-1 (fenced by sync)
        } else {
            asm volatile("cp.async.commit_group;\n" ::: "memory"); // keep count
        }

        const float* Asl = smem + (size_t)(kt & (STAGES - 1)) * STAGE_FLTS;
        const float* Bsl = Asl + A_FLTS;

        // load ALL frags for both k-substeps, then run 32 uninterrupted HMMAs
        unsigned a[2][4][4], b[2][4][2];
        #pragma unroll
        for (int ks = 0; ks < 2; ks++) {
            const int k0 = ks * 8;
            #pragma unroll
            for (int i = 0; i < 4; i++) {
                const int r = wm + i * 16 + g;
                a[ks][i][0] = __float_as_uint(Asl[(r    ) * 20 + k0 + t]);
                a[ks][i][1] = __float_as_uint(Asl[(r + 8) * 20 + k0 + t]);
                a[ks][i][2] = __float_as_uint(Asl[(r    ) * 20 + k0 + t + 4]);
                a[ks][i][3] = __float_as_uint(Asl[(r + 8) * 20 + k0 + t + 4]);
            }
            #pragma unroll
            for (int j = 0; j < 4; j++) {
                const int cn = wn + j * 8 + g;
                b[ks][j][0] = __float_as_uint(Bsl[(k0 + t    ) * 136 + cn]);
                b[ks][j][1] = __float_as_uint(Bsl[(k0 + t + 4) * 136 + cn]);
            }
        }
        #pragma unroll
        for (int ks = 0; ks < 2; ks++)
            #pragma unroll
            for (int i = 0; i < 4; i++)
                #pragma unroll
                for (int j = 0; j < 4; j++) {
                    asm volatile(
                        "mma.sync.aligned.m16n8k8.row.col.f32.tf32.tf32.f32 "
                        "{%0,%1,%2,%3}, {%4,%5,%6,%7}, {%8,%9}, {%0,%1,%2,%3};\n"
                        : "+f"(c[i*4+j][0]), "+f"(c[i*4+j][1]),
                          "+f"(c[i*4+j][2]), "+f"(c[i*4+j][3])
                        : "r"(a[ks][i][0]), "r"(a[ks][i][1]),
                          "r"(a[ks][i][2]), "r"(a[ks][i][3]),
                          "r"(b[ks][j][0]), "r"(b[ks][j][1]));
                }
    }

    // epilogue
    #pragma unroll
    for (int i = 0; i < 4; i++) {
        #pragma unroll
        for (int j = 0; j < 4; j++) {
            const int row = by * 128 + wm + i * 16 + g;
            const int col = bx * 128 + wn + j * 8 + 2 * t;
            if (col < N) {
                float b0 = 0.f, b1 = 0.f;
                if (bias) { b0 = __ldg(&bias[col]); b1 = __ldg(&bias[col + 1]); }
                float2 v0 = make_float2(c[i*4+j][0] + b0, c[i*4+j][1] + b1);
                float2 v1 = make_float2(c[i*4+j][2] + b0, c[i*4+j][3] + b1);
                *(float2*)&C[(size_t)row * N + col]       = v0;
                *(float2*)&C[(size_t)(row + 8) * N + col] = v1;
            }
        }
    }
#undef ISSUE_TILE
}

// ---------------- causal depthwise conv1d (K=4) + SiLU ----------------
__global__ void conv_silu_kernel(const float* __restrict__ conv_w,
                                 const float* __restrict__ conv_b)
{
    int idx = blockIdx.x * blockDim.x + threadIdx.x;
    if (idx >= BL * CONVDIM) return;
    int c = idx % CONVDIM;
    int m = idx / CONVDIM;       // b*L + l
    int l = m % LSEQ;

    float acc = conv_b[c];
    #pragma unroll
    for (int k = 0; k < KCONV; k++) {
        int lk = l - (KCONV - 1) + k;
        if (lk >= 0) {
            acc += g_proj[(size_t)(m - (KCONV - 1) + k) * PROJW + DMODEL + c]
                   * conv_w[c * KCONV + k];
        }
    }
    acc = acc / (1.f + expf(-acc));
    g_conv[(size_t)m * CONVDIM + c] = acc;
}

// ---------------- dt = softplus(dt_raw + bias), dA = exp(dt*A) ----------------
__global__ void dt_kernel(const float* __restrict__ A_log,
                          const float* __restrict__ dt_bias)
{
    int idx = blockIdx.x * blockDim.x + threadIdx.x;
    if (idx >= BL * HEADS) return;
    int h = idx % HEADS;
    int m = idx / HEADS;
    int b = m / LSEQ;
    int l = m % LSEQ;

    float raw = g_proj[(size_t)m * PROJW + DMODEL + CONVDIM + h] + dt_bias[h];
    float dt  = (raw > 20.f) ? raw : log1pf(expf(raw));
    float dA  = expf(dt * (-expf(A_log[h])));
    size_t o  = ((size_t)(b * HEADS + h)) * LSEQ + l;
    g_dt[o] = dt;
    g_dA[o] = dA;
}

// ---------------- selective scan ----------------
// one block per (b,h); 128 threads; thread owns (p = tid>>1) and HALF the
// n-states (8 f32x2 pairs). One shfl_xor(1) combines halves. Operands
// streamed via depth-8 cp.async ring; ONE __syncthreads per step.
#define SD 8

__global__ __launch_bounds__(128, 1)
void scan_kernel(const float* __restrict__ D_param)
{
    const int h   = blockIdx.x;
    const int b   = blockIdx.y;
    const int tid = threadIdx.x;

    __shared__ float s_dt[LSEQ];
    __shared__ float s_dA[LSEQ];
    __shared__ __align__(16) float s_pipe[SD][128];

    {
        const float* dtp = g_dt + ((size_t)(b * HEADS + h)) * LSEQ;
        const float* dAp = g_dA + ((size_t)(b * HEADS + h)) * LSEQ;
        for (int i = tid; i < LSEQ; i += 128) {
            s_dt[i] = dtp[i];
            s_dA[i] = dAp[i];
        }
    }

    const int p    = tid >> 1;
    const int half = tid & 1;
    const float Dh = D_param[h];

    unsigned long long hs[8];
    #pragma unroll
    for (int i = 0; i < 8; i++) hs[i] = 0ull;

    const bool loader = (tid < 32);
    size_t srcoff = 0; int dstoff = 0;
    if (loader) {
        if (tid < 16) { srcoff = (size_t)h * HDIM + tid * 4; dstoff = tid * 4; }
        else          { srcoff = (size_t)DMODEL + (tid - 16) * 4; dstoff = 64 + (tid - 16) * 4; }
    }
    const float* convb = g_conv + (size_t)b * LSEQ * CONVDIM;
    unsigned sbase = (unsigned)__cvta_generic_to_shared(&s_pipe[0][0]);

    // prologue: issue SD-1 tiles
    #pragma unroll
    for (int tt = 0; tt < SD - 1; tt++) {
        if (loader) {
            const float* src = convb + (size_t)tt * CONVDIM + srcoff;
            unsigned dst = sbase + (unsigned)((tt & (SD - 1)) * 128 + dstoff) * 4u;
            asm volatile("cp.async.ca.shared.global [%0], [%1], 16;\n"
                         :: "r"(dst), "l"(src));
        }
        asm volatile("cp.async.commit_group;\n" ::: "memory");
    }

    float* yout = g_y + (size_t)b * LSEQ * DMODEL + h * HDIM + p;

    for (int tc = 0; tc < LSEQ; tc++) {
        asm volatile("cp.async.wait_group 6;\n" ::: "memory");   // step tc ready
        __syncthreads();                                          // + prev compute done

        const int nt = tc + SD - 1;
        if (loader && nt < LSEQ) {
            const float* src = convb + (size_t)nt * CONVDIM + srcoff;
            unsigned dst = sbase + (unsigned)((nt & (SD - 1)) * 128 + dstoff) * 4u;
            asm volatile("cp.async.ca.shared.global [%0], [%1], 16;\n"
                         :: "r"(dst), "l"(src));
        }
        asm volatile("cp.async.commit_group;\n" ::: "memory");

        const float* sl = s_pipe[tc & (SD - 1)];
        float xv  = sl[p];
        float dtv = s_dt[tc];
        float dav = s_dA[tc];
        float coef = dtv * xv;
        unsigned long long c2 = pack2(coef, coef);
        unsigned long long d2 = pack2(dav, dav);
        const unsigned long long* B2 = (const unsigned long long*)(sl + 64) + half * 8;
        const unsigned long long* C2 = (const unsigned long long*)(sl + 96) + half * 8;

        unsigned long long acc0 = 0ull, acc1 = 0ull;
        #pragma unroll
        for (int i = 0; i < 8; i++) {
            unsigned long long u = mul2(c2, B2[i]);
            hs[i] = fma2v(d2, hs[i], u);
            if (i & 1) acc1 = fma2v(hs[i], C2[i], acc1);
            else       acc0 = fma2v(hs[i], C2[i], acc0);
        }
        unsigned long long s = add2(acc0, acc1);
        float mine = lo32(s) + hi32(s);
        float other = __shfl_xor_sync(0xffffffffu, mine, 1);
        if (half == 0) {
            yout[(size_t)tc * DMODEL] = mine + other + Dh * xv;
        }
    }
}

// ---------------- gated RMSNorm (in place; output tf32-rounded for GEMM2) ----------------
__global__ void __launch_bounds__(256)
rmsnorm_kernel(const float* __restrict__ norm_w)
{
    const int m   = blockIdx.x;
    const int tid = threadIdx.x;
    float*       yrow = g_y    + (size_t)m * DMODEL;
    const float* grow = g_proj + (size_t)m * PROJW;   // gate = proj[:, 0:2048]

    float v[8];
    float ss = 0.f;
    #pragma unroll
    for (int k = 0; k < 8; k++) {
        int j = tid + k * 256;
        float gt  = grow[j];
        float val = yrow[j] * (gt / (1.f + expf(-gt)));
        v[k] = val;
        ss += val * val;
    }
    #pragma unroll
    for (int o = 16; o > 0; o >>= 1) ss += __shfl_xor_sync(0xffffffffu, ss, o);

    __shared__ float sred[8];
    if ((tid & 31) == 0) sred[tid >> 5] = ss;
    __syncthreads();
    float tot = sred[0] + sred[1] + sred[2] + sred[3]
              + sred[4] + sred[5] + sred[6] + sred[7];
    float scale = rsqrtf(tot * (1.f / DMODEL) + 1e-6f);

    #pragma unroll
    for (int k = 0; k < 8; k++) {
        int j = tid + k * 256;
        yrow[j] = tf32r(v[k] * scale * norm_w[j]);
    }
}

// ---------------- launch ----------------
extern "C" void kernel_launch(void* const* d_in, const int* in_sizes, int n_in,
                              void* d_out, int out_size)
{
    const float* x       = (const float*)d_in[0];
    const float* W_in    = (const float*)d_in[1];
    const float* b_in    = (const float*)d_in[2];
    const float* conv_w  = (const float*)d_in[3];
    const float* conv_b  = (const float*)d_in[4];
    const float* A_log   = (const float*)d_in[5];
    const float* dt_bias = (const float*)d_in[6];
    const float* D_par   = (const float*)d_in[7];
    const float* norm_w  = (const float*)d_in[8];
    const float* W_out   = (const float*)d_in[9];
    float* out = (float*)d_out;

    float *proj, *yb, *xa, *wa, *wb;
    cudaGetSymbolAddress((void**)&proj, g_proj);
    cudaGetSymbolAddress((void**)&yb,   g_y);
    cudaGetSymbolAddress((void**)&xa,   g_xa);
    cudaGetSymbolAddress((void**)&wa,   g_wa);
    cudaGetSymbolAddress((void**)&wb,   g_wb);

    cudaFuncSetAttribute(mma_gemm, cudaFuncAttributeMaxDynamicSharedMemorySize,
                         GEMM_SMEM);

    // 0) tf32-round GEMM operands
    {
        int n4x = (BL * DMODEL) / 4;
        round_tf32_kernel<<<(n4x + 255) / 256, 256>>>(x, xa, n4x);
        int n4a = (DMODEL * PROJW) / 4;
        round_tf32_kernel<<<(n4a + 255) / 256, 256>>>(W_in, wa, n4a);
        int n4b = (DMODEL * DMODEL) / 4;
        round_tf32_kernel<<<(n4b + 255) / 256, 256>>>(W_out, wb, n4b);
    }
    // 1) proj = x @ W_in + b_in        (8192 x 4192, K=2048)
    {
        dim3 grid((PROJW + 127) / 128, BL / 128);
        mma_gemm<<<grid, 256, GEMM_SMEM>>>(xa, wa, b_in, proj, BL, PROJW, DMODEL);
    }
    // 2) causal depthwise conv + SiLU
    {
        int total = BL * CONVDIM;
        conv_silu_kernel<<<(total + 255) / 256, 256>>>(conv_w, conv_b);
    }
    // 3) dt / dA
    {
        int total = BL * HEADS;
        dt_kernel<<<(total + 255) / 256, 256>>>(A_log, dt_bias);
    }
    // 4) selective scan (+ D skip)
    scan_kernel<<<dim3(HEADS, BATCH), 128>>>(D_par);
    // 5) gated RMSNorm (tf32-rounds y)
    rmsnorm_kernel<<<BL, 256>>>(norm_w);
    // 6) out = y @ W_out               (8192 x 2048, K=2048)
    {
        dim3 grid(DMODEL / 128, BL / 128);
        mma_gemm<<<grid, 256, GEMM_SMEM>>>(yb, wb, nullptr, out, BL, DMODEL, DMODEL);
    }
}